// round 16
// baseline (speedup 1.0000x reference)
#include <cuda_runtime.h>

#define VV   128
#define HH   512
#define BB   8192
#define OUTW 256   // 2*V

#define VG    8            // v's per GEMM block
#define KT    32           // k's per GEMM block
#define KS2   (HH / KT)    // 16 k-segments
#define VGN2  (VV / VG)    // 16 v-groups
#define NGEMM 256          // 16 vg x 16 ks
#define NZERO 256
#define NEXTR 1024         // 8 rows each (1 row per warp)
#define NBLK  (NGEMM + NZERO + NEXTR)
#define THR   256

// Scratch (alloc-free rule: __device__ globals). g_vgdone monotonic -> graph
// replay safe; tables identical every replay.
__device__ float    g_part[KS2 * VV * OUTW];   // 2 MB partial sums
__device__ int      g_loc[VV];
__device__ int      g_scale[VV];
__device__ int      g_idx[BB];                 // packed (i0 | i1<<8) per row
__device__ unsigned g_vgdone[VGN2];            // 16 increments per vg/replay

// Monotone orderable key for float argmax with first-index tie-break.
__device__ __forceinline__ unsigned long long amax_key(float f, int col)
{
    unsigned int u = __float_as_uint(f);
    u = (u & 0x80000000u) ? ~u : (u | 0x80000000u);
    return ((unsigned long long)u << 32) | (unsigned long long)(127 - col);
}

__device__ __forceinline__ void cp_async16(void* smem_dst, const void* gmem_src)
{
    unsigned long long sa = __cvta_generic_to_shared(smem_dst);
    asm volatile("cp.async.cg.shared.global [%0], [%1], 16;\n"
                 :: "r"((unsigned)sa), "l"(gmem_src) : "memory");
}

// ---------------------------------------------------------------------------
// K1: three INDEPENDENT duties in one grid (no cross-duty sync at all):
//   blocks [0,256):      GEMM partials + per-vgroup argmax tables
//   blocks [256,512):    zero-fill the entire output (8 MB constant stores)
//   blocks [512,1536):   extract (i0,i1) per row -> g_idx (8 MB reads)
// The K1->K2 kernel boundary is the only ordering point.
// ---------------------------------------------------------------------------
__global__ void __launch_bounds__(THR)
k1_all(const float* __restrict__ in, const float* __restrict__ W1,
       const float* __restrict__ b1, const float* __restrict__ W2,
       const float* __restrict__ b2, float* __restrict__ out)
{
    const int blk = blockIdx.x;
    const int t = threadIdx.x;
    const int wid = t >> 5, lane = t & 31;

    __shared__ __align__(16) float smW2[KT][OUTW];   // 32 KB (GEMM duty only)
    __shared__ __align__(16) float h[KT][VG];        // 1 KB
    __shared__ unsigned long long skey[VG * 2];
    __shared__ int s_last;

    if (blk >= NGEMM + NZERO) {
        // ================= extract duty: 8 rows, 1 per warp =================
        const int row = (blk - NGEMM - NZERO) * 8 + wid;
        const float4* r4 = reinterpret_cast<const float4*>(
            in + (size_t)row * OUTW);

        const float4 a = r4[lane];          // x0 chunk
        const float4 c = r4[32 + lane];     // x1 chunk

        const int m0 = (a.x == 1.0f) | ((a.y == 1.0f) << 1) |
                       ((a.z == 1.0f) << 2) | ((a.w == 1.0f) << 3);
        const int m1 = (c.x == 1.0f) | ((c.y == 1.0f) << 1) |
                       ((c.z == 1.0f) << 2) | ((c.w == 1.0f) << 3);

        // one-hot -> index = sum of the single nonzero lane contribution
        const int li0 = m0 ? (lane * 4 + __ffs(m0) - 1) : 0;
        const int li1 = m1 ? (lane * 4 + __ffs(m1) - 1) : 0;
        const int i0 = __reduce_add_sync(0xFFFFFFFFu, li0);
        const int i1 = __reduce_add_sync(0xFFFFFFFFu, li1);

        if (lane == 0) g_idx[row] = i0 | (i1 << 8);
        return;
    }

    if (blk >= NGEMM) {
        // ================= zero duty: 32 KB contiguous per block ============
        float4* o4 = reinterpret_cast<float4*>(out) + (blk - NGEMM) * 2048;
        const float4 z4 = make_float4(0.f, 0.f, 0.f, 0.f);
        #pragma unroll
        for (int i = 0; i < 8; ++i)
            o4[i * THR + t] = z4;
        return;
    }

    // ===================== GEMM duty ========================================
    const int vg = blk & (VGN2 - 1);   // 0..15
    const int ks = blk >> 4;           // 0..15
    const int v0 = vg * VG;
    const int k0 = ks * KT;
    const int c = t;

    // Stage W2 tile [k0,k0+32) x 256 via cp.async (HW-pipelined, zero regs).
    {
        const float4* __restrict__ g4 =
            reinterpret_cast<const float4*>(W2 + (size_t)k0 * OUTW);
        float4* s4 = reinterpret_cast<float4*>(&smW2[0][0]);
        #pragma unroll
        for (int i = 0; i < 8; ++i)
            cp_async16(&s4[t + i * THR], &g4[t + i * THR]);
        asm volatile("cp.async.commit_group;\n" ::: "memory");
    }

    // h[k][v] = relu(W1[v0+v][k0+k] + b1[k0+k]); 256 entries, 1/thread.
    {
        const int v = t >> 5, k = t & (KT - 1);
        h[k][v] = fmaxf(W1[(size_t)(v0 + v) * HH + k0 + k] + b1[k0 + k], 0.0f);
    }
    if (t < VG * 2) skey[t] = 0ULL;

    asm volatile("cp.async.wait_group 0;\n" ::: "memory");
    __syncthreads();

    // Thread-per-column accumulate from SMEM (29-cyc latency).
    float acc[VG];
    #pragma unroll
    for (int v = 0; v < VG; ++v) acc[v] = 0.0f;

    #pragma unroll 4
    for (int k = 0; k < KT; ++k) {
        const float w = smW2[k][c];                       // conflict-free LDS
        const float4 h03 = *reinterpret_cast<const float4*>(&h[k][0]);
        const float4 h47 = *reinterpret_cast<const float4*>(&h[k][4]);
        acc[0] = fmaf(h03.x, w, acc[0]);
        acc[1] = fmaf(h03.y, w, acc[1]);
        acc[2] = fmaf(h03.z, w, acc[2]);
        acc[3] = fmaf(h03.w, w, acc[3]);
        acc[4] = fmaf(h47.x, w, acc[4]);
        acc[5] = fmaf(h47.y, w, acc[5]);
        acc[6] = fmaf(h47.z, w, acc[6]);
        acc[7] = fmaf(h47.w, w, acc[7]);
    }

    #pragma unroll
    for (int v = 0; v < VG; ++v)                          // coalesced per v
        g_part[((size_t)ks * VV + v0 + v) * OUTW + c] = acc[v];

    // ---- vgroup completion: 16th arriver reduces + argmaxes its 8 v's ------
    if (t == 0) {
        __threadfence();                                  // release partials
        const unsigned my = atomicAdd(&g_vgdone[vg], 1u);
        s_last = ((my & (KS2 - 1u)) == (KS2 - 1u));
    }
    __syncthreads();

    if (s_last) {
        const float bb = b2[c];
        const int half = c >> 7;                          // warp-uniform
        const int col = c & 127;

        #pragma unroll
        for (int v = 0; v < VG; ++v) {
            float ps[KS2];
            #pragma unroll
            for (int s8 = 0; s8 < KS2; ++s8)              // 16 indep loads
                ps[s8] = g_part[((size_t)s8 * VV + v0 + v) * OUTW + c];
            float sum = bb;
            #pragma unroll
            for (int s8 = 0; s8 < KS2; ++s8) sum += ps[s8];

            unsigned long long key = amax_key(sum, col);
            #pragma unroll
            for (int off = 16; off > 0; off >>= 1) {
                const unsigned long long o = __shfl_xor_sync(0xFFFFFFFFu, key, off);
                if (o > key) key = o;
            }
            if (lane == 0) atomicMax(&skey[v * 2 + half], key);
        }
        __syncthreads();

        if (t < VG) {
            g_loc[v0 + t]   = 127 - (int)(skey[t * 2]     & 0xFFFFFFFFULL);
            g_scale[v0 + t] = 127 - (int)(skey[t * 2 + 1] & 0xFFFFFFFFULL);
        }
    }
}

// ---------------------------------------------------------------------------
// K2: scatter. One thread per row; g_idx + tables -> TWO 4-byte stores into
// the pre-zeroed output: out[b][i0] = 1 (x0 reconstructed exactly) and the
// flow one-hot out[b][128 + (l + i1*s)%128] = 1 (skipped when s==0).
// ---------------------------------------------------------------------------
__global__ void __launch_bounds__(THR)
k2_scatter(float* __restrict__ out)
{
    const int row = blockIdx.x * THR + threadIdx.x;
    const int pk = g_idx[row];
    const int i0 = pk & 255;
    const int i1 = pk >> 8;
    const int l = g_loc[i0];
    const int s = g_scale[i0];
    float* orow = out + (size_t)row * OUTW;
    orow[i0] = 1.0f;
    if (s != 0) {
        const int tcol = (l + i1 * s) & (VV - 1);
        orow[VV + tcol] = 1.0f;
    }
}

// ---------------------------------------------------------------------------
// Launch. Inputs in setup_inputs() order: inputs, W1, b1, W2, b2.
// ---------------------------------------------------------------------------
extern "C" void kernel_launch(void* const* d_in, const int* in_sizes, int n_in,
                              void* d_out, int out_size)
{
    const float* in = (const float*)d_in[0];
    const float* W1 = (const float*)d_in[1];
    const float* b1 = (const float*)d_in[2];
    const float* W2 = (const float*)d_in[3];
    const float* b2 = (const float*)d_in[4];
    float* out = (float*)d_out;

    k1_all<<<NBLK, THR>>>(in, W1, b1, W2, b2, out);
    k2_scatter<<<BB / THR, THR>>>(out);
}

// round 17
// speedup vs baseline: 1.0133x; 1.0133x over previous
#include <cuda_runtime.h>

#define VV   128
#define HH   512
#define BB   8192
#define OUTW 256   // 2*V

#define VG    8            // v's per GEMM block
#define KT    32           // k's per GEMM block
#define KS2   (HH / KT)    // 16 k-segments
#define VGN2  (VV / VG)    // 16 v-groups
#define NGEMM 256          // 16 vg x 16 ks
#define NROW  512          // 16 rows each
#define NBLK  (NGEMM + NROW)
#define THR   256

// Scratch (alloc-free rule: __device__ globals). All counters monotonic
// (never reset) -> CUDA-graph replay safe; tables identical each replay.
__device__ float    g_part[KS2 * VV * OUTW];   // 2 MB partial sums
__device__ int      g_loc[VV];
__device__ int      g_scale[VV];
__device__ unsigned g_vgdone[VGN2];            // 16 increments per vg/replay
__device__ unsigned g_ready = 0u;              // 16 increments per replay
__device__ unsigned g_row_epoch = 0u;          // 512 increments per replay

// Monotone orderable key for float argmax with first-index tie-break.
__device__ __forceinline__ unsigned long long amax_key(float f, int col)
{
    unsigned int u = __float_as_uint(f);
    u = (u & 0x80000000u) ? ~u : (u | 0x80000000u);
    return ((unsigned long long)u << 32) | (unsigned long long)(127 - col);
}

__device__ __forceinline__ void cp_async16(void* smem_dst, const void* gmem_src)
{
    unsigned long long sa = __cvta_generic_to_shared(smem_dst);
    asm volatile("cp.async.cg.shared.global [%0], [%1], 16;\n"
                 :: "r"((unsigned)sa), "l"(gmem_src) : "memory");
}

// ---------------------------------------------------------------------------
// ONE kernel, ONE wave (768 blocks <= 888 co-resident at 33KB smem):
//   blocks [0,256):   GEMM partials + per-vgroup argmax tables + g_ready.
//   blocks [256,768): 16 rows each: zero-stores (independent of loads!) +
//                     loads + ballot-extract, short table-wait, scatter the
//                     two 1.0f's per row. No second kernel, no g_idx trip.
// GEMM blocks never wait on anything -> no deadlock; they are bids 0..255
// (wave-1 guaranteed), so row-block polls always make progress.
// ---------------------------------------------------------------------------
__global__ void __launch_bounds__(THR)
fused_kernel(const float* __restrict__ in, const float* __restrict__ W1,
             const float* __restrict__ b1, const float* __restrict__ W2,
             const float* __restrict__ b2, float* __restrict__ out)
{
    const int blk = blockIdx.x;
    const int t = threadIdx.x;
    const int wid = t >> 5, lane = t & 31;

    __shared__ __align__(16) float smW2[KT][OUTW];   // 32 KB (GEMM duty)
    __shared__ __align__(16) float h[KT][VG];        // 1 KB
    __shared__ unsigned long long skey[VG * 2];
    __shared__ int s_last;
    __shared__ unsigned s_target;

    if (blk >= NGEMM) {
        // ================= row duty: 16 rows (8 warps x 2 rows) =============
        const int rb = blk - NGEMM;

        // Replay-safe epoch target: tickets of replay r are [512r, 512r+512)
        // -> need g_ready >= 16*(r+1).
        if (t == 0) {
            const unsigned my = atomicAdd(&g_row_epoch, 1u);
            s_target = ((my >> 9) + 1u) * 16u;
        }

        const int r0 = rb * 16 + wid * 2;
        const float4* in4 = reinterpret_cast<const float4*>(in);
        float4* out4 = reinterpret_cast<float4*>(out);
        const size_t base0 = (size_t)r0 * 64;
        const size_t base1 = base0 + 64;

        // Zero-stores are CONSTANT (output reconstructed from indices):
        // issue them up front, independent of the loads.
        const float4 z4 = make_float4(0.f, 0.f, 0.f, 0.f);
        out4[base0 + lane] = z4;
        out4[base0 + 32 + lane] = z4;
        out4[base1 + lane] = z4;
        out4[base1 + 32 + lane] = z4;

        // Front-batched independent loads (MLP 4 x 16B per lane).
        const float4 a0 = in4[base0 + lane];
        const float4 c0 = in4[base0 + 32 + lane];
        const float4 a1 = in4[base1 + lane];
        const float4 c1 = in4[base1 + 32 + lane];

        // x0/x1 are EXACT one-hots -> index = reduce_add of the single
        // nonzero lane contribution.
        const int ma0 = (a0.x == 1.0f) | ((a0.y == 1.0f) << 1) |
                        ((a0.z == 1.0f) << 2) | ((a0.w == 1.0f) << 3);
        const int mc0 = (c0.x == 1.0f) | ((c0.y == 1.0f) << 1) |
                        ((c0.z == 1.0f) << 2) | ((c0.w == 1.0f) << 3);
        const int ma1 = (a1.x == 1.0f) | ((a1.y == 1.0f) << 1) |
                        ((a1.z == 1.0f) << 2) | ((a1.w == 1.0f) << 3);
        const int mc1 = (c1.x == 1.0f) | ((c1.y == 1.0f) << 1) |
                        ((c1.z == 1.0f) << 2) | ((c1.w == 1.0f) << 3);

        const int i0_r0 = __reduce_add_sync(0xFFFFFFFFu,
                              ma0 ? (lane * 4 + __ffs(ma0) - 1) : 0);
        const int i1_r0 = __reduce_add_sync(0xFFFFFFFFu,
                              mc0 ? (lane * 4 + __ffs(mc0) - 1) : 0);
        const int i0_r1 = __reduce_add_sync(0xFFFFFFFFu,
                              ma1 ? (lane * 4 + __ffs(ma1) - 1) : 0);
        const int i1_r1 = __reduce_add_sync(0xFFFFFFFFu,
                              mc1 ? (lane * 4 + __ffs(mc1) - 1) : 0);

        // Wait for this replay's 16 vgroup tables.
        if (t == 0) {
            while ((int)(*(volatile unsigned*)&g_ready - s_target) < 0)
                __nanosleep(64);
            __threadfence();                              // acquire tables
        }
        __syncthreads();   // also orders our zero-stores before the scatters

        // Scatter: lanes 0 and 1 of each warp own rows r0 and r0+1.
        if (lane < 2) {
            const int i0 = lane ? i0_r1 : i0_r0;
            const int i1 = lane ? i1_r1 : i1_r0;
            const int l = g_loc[i0];
            const int s = g_scale[i0];
            float* orow = out + (size_t)(r0 + lane) * OUTW;
            orow[i0] = 1.0f;                              // x0 reconstructed
            if (s != 0) {
                const int tcol = (l + i1 * s) & (VV - 1);
                orow[VV + tcol] = 1.0f;
            }
        }
        return;
    }

    // ===================== GEMM duty ========================================
    const int vg = blk & (VGN2 - 1);   // 0..15
    const int ks = blk >> 4;           // 0..15
    const int v0 = vg * VG;
    const int k0 = ks * KT;
    const int c = t;

    // Stage W2 tile [k0,k0+32) x 256 via cp.async (HW-pipelined, zero regs).
    {
        const float4* __restrict__ g4 =
            reinterpret_cast<const float4*>(W2 + (size_t)k0 * OUTW);
        float4* s4 = reinterpret_cast<float4*>(&smW2[0][0]);
        #pragma unroll
        for (int i = 0; i < 8; ++i)
            cp_async16(&s4[t + i * THR], &g4[t + i * THR]);
        asm volatile("cp.async.commit_group;\n" ::: "memory");
    }

    // h[k][v] = relu(W1[v0+v][k0+k] + b1[k0+k]); 256 entries, 1/thread.
    {
        const int v = t >> 5, k = t & (KT - 1);
        h[k][v] = fmaxf(W1[(size_t)(v0 + v) * HH + k0 + k] + b1[k0 + k], 0.0f);
    }
    if (t < VG * 2) skey[t] = 0ULL;

    asm volatile("cp.async.wait_group 0;\n" ::: "memory");
    __syncthreads();

    // Thread-per-column accumulate from SMEM (29-cyc latency).
    float acc[VG];
    #pragma unroll
    for (int v = 0; v < VG; ++v) acc[v] = 0.0f;

    #pragma unroll 4
    for (int k = 0; k < KT; ++k) {
        const float w = smW2[k][c];                       // conflict-free LDS
        const float4 h03 = *reinterpret_cast<const float4*>(&h[k][0]);
        const float4 h47 = *reinterpret_cast<const float4*>(&h[k][4]);
        acc[0] = fmaf(h03.x, w, acc[0]);
        acc[1] = fmaf(h03.y, w, acc[1]);
        acc[2] = fmaf(h03.z, w, acc[2]);
        acc[3] = fmaf(h03.w, w, acc[3]);
        acc[4] = fmaf(h47.x, w, acc[4]);
        acc[5] = fmaf(h47.y, w, acc[5]);
        acc[6] = fmaf(h47.z, w, acc[6]);
        acc[7] = fmaf(h47.w, w, acc[7]);
    }

    #pragma unroll
    for (int v = 0; v < VG; ++v)                          // coalesced per v
        g_part[((size_t)ks * VV + v0 + v) * OUTW + c] = acc[v];

    // ---- vgroup completion: 16th arriver reduces + argmaxes its 8 v's ------
    if (t == 0) {
        __threadfence();                                  // release partials
        const unsigned my = atomicAdd(&g_vgdone[vg], 1u);
        s_last = ((my & (KS2 - 1u)) == (KS2 - 1u));
    }
    __syncthreads();

    if (s_last) {
        const float bb = b2[c];
        const int half = c >> 7;                          // warp-uniform
        const int col = c & 127;

        #pragma unroll
        for (int v = 0; v < VG; ++v) {
            float ps[KS2];
            #pragma unroll
            for (int s8 = 0; s8 < KS2; ++s8)              // 16 indep loads
                ps[s8] = g_part[((size_t)s8 * VV + v0 + v) * OUTW + c];
            float sum = bb;
            #pragma unroll
            for (int s8 = 0; s8 < KS2; ++s8) sum += ps[s8];

            unsigned long long key = amax_key(sum, col);
            #pragma unroll
            for (int off = 16; off > 0; off >>= 1) {
                const unsigned long long o = __shfl_xor_sync(0xFFFFFFFFu, key, off);
                if (o > key) key = o;
            }
            if (lane == 0) atomicMax(&skey[v * 2 + half], key);
        }
        __syncthreads();

        if (t < VG) {
            g_loc[v0 + t]   = 127 - (int)(skey[t * 2]     & 0xFFFFFFFFULL);
            g_scale[v0 + t] = 127 - (int)(skey[t * 2 + 1] & 0xFFFFFFFFULL);
        }
        __syncthreads();
        if (t == 0) {
            __threadfence();                              // release tables
            atomicAdd(&g_ready, 1u);
        }
    }
}

// ---------------------------------------------------------------------------
// Launch: ONE kernel, one wave. Inputs: inputs, W1, b1, W2, b2.
// ---------------------------------------------------------------------------
extern "C" void kernel_launch(void* const* d_in, const int* in_sizes, int n_in,
                              void* d_out, int out_size)
{
    const float* in = (const float*)d_in[0];
    const float* W1 = (const float*)d_in[1];
    const float* b1 = (const float*)d_in[2];
    const float* W2 = (const float*)d_in[3];
    const float* b2 = (const float*)d_in[4];
    float* out = (float*)d_out;

    fused_kernel<<<NBLK, THR>>>(in, W1, b1, W2, b2, out);
}